// round 15
// baseline (speedup 1.0000x reference)
#include <cuda_runtime.h>
#include <cuda_fp16.h>
#include <cstdint>
#include <math.h>

#define TOK 100352          // B * H * W tokens

// ---------------- scratch (device globals; no allocation allowed) -----------
__device__ __half  g_qkvh[(size_t)TOK * 576];   // qkv fp16, windowed rows
__device__ float   g_xbuf[(size_t)TOK * 192];   // running x (token layout)
__device__ __half  g_xn  [(size_t)TOK * 192];   // LN out fp16
__device__ __half  g_att [(size_t)TOK * 192];   // attention out fp16
__device__ __half  g_hid [(size_t)TOK * 768];   // fc1 out fp16
__device__ __half  g_wt  [2 * 442368];          // transposed weights fp16 [N,K]

// ---------------- helpers -----------------------------------------------------
__device__ __forceinline__ uint32_t smem_u32(const void* p) {
    uint32_t a;
    asm("{ .reg .u64 t; cvta.to.shared.u64 t, %1; cvt.u32.u64 %0, t; }" : "=r"(a) : "l"(p));
    return a;
}
#define CP_ASYNC16(dst, src) \
    asm volatile("cp.async.cg.shared.global [%0], [%1], 16;" :: "r"(dst), "l"(src))
#define CP_COMMIT()  asm volatile("cp.async.commit_group;" ::: "memory")
#define MMA_FP16(d, a, b) \
    asm volatile("mma.sync.aligned.m16n8k16.row.col.f32.f16.f16.f32 " \
        "{%0,%1,%2,%3}, {%4,%5,%6,%7}, {%8,%9}, {%0,%1,%2,%3};" \
        : "+f"((d)[0]), "+f"((d)[1]), "+f"((d)[2]), "+f"((d)[3]) \
        : "r"((a)[0]), "r"((a)[1]), "r"((a)[2]), "r"((a)[3]), "r"((b)[0]), "r"((b)[1]))

// ---------------- weight transpose (both layers), fp16 ----------------------
__global__ void wprep_kernel(const float* __restrict__ W, __half* __restrict__ T,
                             int K, int N, int strideT) {
    int i = blockIdx.x * blockDim.x + threadIdx.x;
    int perL = K * N;
    if (i >= 2 * perL) return;
    int d = i / perL, r = i - d * perL;
    int n = r / K, k = r - n * K;
    T[(size_t)d * strideT + n * K + k] = __float2half(W[(size_t)d * perL + (size_t)k * N + n]);
}

// ---------------- LayerNorm (+ optional shift/window gather), fp16 out -------
__global__ void ln_kernel(const float* __restrict__ x, const float* __restrict__ g,
                          const float* __restrict__ bta, __half* __restrict__ oh,
                          int shift, int gather)
{
    int warp = (blockIdx.x * blockDim.x + threadIdx.x) >> 5;
    int lane = threadIdx.x & 31;
    if (warp >= TOK) return;
    int row = warp;
    const float* xi;
    if (gather) {
        int n  = row % 49;
        int wg = row / 49;
        int w  = wg & 63;
        int b  = wg >> 6;
        int hr = (w >> 3) * 7 + n / 7 + shift; if (hr >= 56) hr -= 56;
        int wc = (w & 7)  * 7 + n % 7 + shift; if (wc >= 56) wc -= 56;
        xi = x + ((size_t)b * 3136 + hr * 56 + wc) * 192;
    } else {
        xi = x + (size_t)row * 192;
    }
    float v[6];
    float s = 0.f, sq = 0.f;
#pragma unroll
    for (int q = 0; q < 6; q++) {
        v[q] = xi[lane + 32 * q];
        s += v[q]; sq += v[q] * v[q];
    }
#pragma unroll
    for (int o = 16; o; o >>= 1) {
        s  += __shfl_xor_sync(0xffffffffu, s,  o);
        sq += __shfl_xor_sync(0xffffffffu, sq, o);
    }
    float mean = s * (1.f / 192.f);
    float var  = sq * (1.f / 192.f) - mean * mean;
    float rstd = rsqrtf(var + 1e-5f);
#pragma unroll
    for (int q = 0; q < 6; q++) {
        int ch = lane + 32 * q;
        float y = (v[q] - mean) * rstd * g[ch] + bta[ch];
        oh[(size_t)row * 192 + ch] = __float2half(y);
    }
}

// ---------------- Windowed attention -----------------------------------------
// One block per (window, head). qkv fp16; simple coalesced per-element loads.
// Q rows in registers, K rows at stride-36 floats, V transposed (stride 52).
__global__ void attn_kernel(const __half* __restrict__ qkv, const float* __restrict__ bt,
                            __half* __restrict__ oh, int shifted)
{
    int blk  = blockIdx.x;
    int head = blk % 6;
    int win  = blk / 6;          // 0..2047
    int w    = win & 63;
    int wh   = w >> 3, ww = w & 7;

    __shared__ float4 qs4[49 * 8];
    __shared__ float4 ks4[49 * 9];       // row stride 36 floats
    __shared__ float4 vs4[32 * 13];      // V transposed: [d][j], row stride 52 floats
    __shared__ float  prow[4][52];
    __shared__ int    lab[49];

    int tid = threadIdx.x;
    const float scale = 0.17677669529663687f;  // 1/sqrt(32)
    const __half* base = qkv + (size_t)win * 49 * 576 + head * 32;
    float* qsf = (float*)qs4;
    float* ksf = (float*)ks4;
    float* vsf = (float*)vs4;
    for (int i = tid; i < 49 * 32; i += 128) {
        int t = i >> 5, d = i & 31;
        const __half* p = base + (size_t)t * 576 + d;
        qsf[t * 32 + d] = __half2float(p[0]) * scale;
        ksf[t * 36 + d] = __half2float(p[192]);
        vsf[d * 52 + t] = __half2float(p[384]);      // transposed
    }
    if (shifted && tid < 49) {
        int r = tid / 7, c = tid % 7;
        int hr = wh * 7 + r, wc = ww * 7 + c;
        int lr = (hr < 49) ? 0 : (hr < 53 ? 1 : 2);
        int lc = (wc < 49) ? 0 : (wc < 53 ? 1 : 2);
        lab[tid] = lr * 3 + lc;
    }
    __syncthreads();

    int warp = tid >> 5, lane = tid & 31;
    for (int i = warp; i < 49; i += 4) {
        float4 q[8];
#pragma unroll
        for (int t = 0; t < 8; t++) q[t] = qs4[i * 8 + t];
        int yi = i / 7, xi = i % 7;
        float s0, s1 = -1e30f;
        {
            int j = lane;
            float acc = 0.f;
#pragma unroll
            for (int t = 0; t < 8; t++) {
                float4 k = ks4[j * 9 + t];
                acc += q[t].x * k.x + q[t].y * k.y + q[t].z * k.z + q[t].w * k.w;
            }
            int yj = j / 7, xj = j % 7;
            acc += bt[((yi - yj + 6) * 13 + (xi - xj + 6)) * 6 + head];
            if (shifted && lab[i] != lab[j]) acc -= 100.f;
            s0 = acc;
        }
        if (lane + 32 < 49) {
            int j = lane + 32;
            float acc = 0.f;
#pragma unroll
            for (int t = 0; t < 8; t++) {
                float4 k = ks4[j * 9 + t];
                acc += q[t].x * k.x + q[t].y * k.y + q[t].z * k.z + q[t].w * k.w;
            }
            int yj = j / 7, xj = j % 7;
            acc += bt[((yi - yj + 6) * 13 + (xi - xj + 6)) * 6 + head];
            if (shifted && lab[i] != lab[j]) acc -= 100.f;
            s1 = acc;
        }
        float m = fmaxf(s0, s1);
#pragma unroll
        for (int o = 16; o; o >>= 1) m = fmaxf(m, __shfl_xor_sync(0xffffffffu, m, o));
        float e0 = __expf(s0 - m);
        float e1 = (lane + 32 < 49) ? __expf(s1 - m) : 0.f;
        float sum = e0 + e1;
#pragma unroll
        for (int o = 16; o; o >>= 1) sum += __shfl_xor_sync(0xffffffffu, sum, o);
        float inv = 1.f / sum;
        prow[warp][lane] = e0 * inv;
        if (lane + 32 < 49) prow[warp][lane + 32] = e1 * inv;
        __syncwarp();
        // PV: lane = output dim d; vectorized over j (12 x float4 + 1 tail)
        const float4* pr4 = (const float4*)&prow[warp][0];
        float acc = 0.f;
#pragma unroll
        for (int q4 = 0; q4 < 12; q4++) {
            float4 p = pr4[q4];
            float4 v = vs4[lane * 13 + q4];
            acc += p.x * v.x + p.y * v.y + p.z * v.z + p.w * v.w;
        }
        acc += prow[warp][48] * vsf[lane * 52 + 48];
        oh[((size_t)win * 49 + i) * 192 + head * 32 + lane] = __float2half(acc);
        __syncwarp();
    }
}

// ---------------- warp-MMA fp16 GEMM (single-term, K-chunk 64) ---------------
// CTA 128x64, 256 threads (4x2 warps, warp tile 32x32), K chunks of 64,
// 2-stage cp.async pipeline, XOR-swizzled smem (128B rows, seg^(row&7)).
// EPI 0: +bias -> fp16 Ch       EPI 1: +bias, GELU -> fp16 Ch
// EPI 2: +bias +res -> fp32 Cf  EPI 3: +bias, window-reverse remap, +res -> fp32
#define STG 12288   // halfs per stage (24576 B): A 16K + B 8K

template <int EPI>
__global__ void __launch_bounds__(256)
tc_gemm(const __half* __restrict__ Ah, const __half* __restrict__ Bw,
        const float* __restrict__ bias, float* __restrict__ Cf,
        __half* __restrict__ Ch,
        const float* __restrict__ res, int M, int N, int K, int shift)
{
    __shared__ __half smem[2 * STG];   // 49152 B
    const int tid  = threadIdx.x;
    const int wid  = tid >> 5, lane = tid & 31;
    const int m0   = blockIdx.y * 128, n0 = blockIdx.x * 64;
    const int wm   = (wid & 3) * 32;          // warp row offset
    const int wn   = (wid >> 2) * 32;         // warp col offset
    const uint32_t sbase = smem_u32(smem);

    float acc[2][4][4];
#pragma unroll
    for (int a = 0; a < 2; a++)
#pragma unroll
        for (int b = 0; b < 4; b++)
#pragma unroll
            for (int c = 0; c < 4; c++) acc[a][b][c] = 0.f;

    const int nch = K >> 6;

    // ---- stage loader: A 128x64 (1024 x 16B) + B 64x64 (512 x 16B) ----
    auto load_stage = [&](int c, int s) {
        int kc = c * 64;
        uint32_t st = sbase + s * (STG * 2);
#pragma unroll
        for (int t = 0; t < 4; t++) {
            int idx = tid + t * 256;                  // 0..1023
            int row = idx >> 3, seg = idx & 7;
            const __half* src = Ah + (size_t)(m0 + row) * K + kc + seg * 8;
            uint32_t d = st + row * 128 + ((seg ^ (row & 7)) * 16);
            CP_ASYNC16(d, src);
        }
#pragma unroll
        for (int t = 0; t < 2; t++) {
            int idx = tid + t * 256;                  // 0..511
            int row = idx >> 3, seg = idx & 7;
            const __half* src = Bw + (size_t)(n0 + row) * K + kc + seg * 8;
            uint32_t d = st + 16384 + row * 128 + ((seg ^ (row & 7)) * 16);
            CP_ASYNC16(d, src);
        }
        CP_COMMIT();
    };

    const int i8  = lane & 7;     // ldmatrix row-within-tile
    const int mat = lane >> 3;    // ldmatrix matrix index

    auto compute_stage = [&](int s) {
        uint32_t st = sbase + s * (STG * 2);
        uint32_t aB = st;
        uint32_t bB = st + 16384;
#pragma unroll
        for (int ks = 0; ks < 4; ks++) {
            uint32_t a[2][4], b[4][2];
#pragma unroll
            for (int mt = 0; mt < 2; mt++) {
                int row = wm + mt * 16 + ((mat & 1) << 3) + i8;
                int cch = ks * 2 + (mat >> 1);            // 8-elem chunk idx (0..7)
                uint32_t addr = aB + row * 128 + ((cch ^ (row & 7)) << 4);
                asm volatile("ldmatrix.sync.aligned.m8n8.x4.shared.b16 {%0,%1,%2,%3}, [%4];"
                    : "=r"(a[mt][0]), "=r"(a[mt][1]), "=r"(a[mt][2]), "=r"(a[mt][3])
                    : "r"(addr));
            }
#pragma unroll
            for (int p = 0; p < 2; p++) {
                // B fragment: [N,K] K-contiguous -> NON-trans ldmatrix
                int row = wn + p * 16 + ((mat >> 1) << 3) + i8;
                int cch = ks * 2 + (mat & 1);
                uint32_t addr = bB + row * 128 + ((cch ^ (row & 7)) << 4);
                uint32_t r0, r1, r2, r3;
                asm volatile("ldmatrix.sync.aligned.m8n8.x4.shared.b16 {%0,%1,%2,%3}, [%4];"
                    : "=r"(r0), "=r"(r1), "=r"(r2), "=r"(r3) : "r"(addr));
                b[p * 2][0] = r0; b[p * 2][1] = r1;
                b[p * 2 + 1][0] = r2; b[p * 2 + 1][1] = r3;
            }
#pragma unroll
            for (int mt = 0; mt < 2; mt++)
#pragma unroll
                for (int nt = 0; nt < 4; nt++)
                    MMA_FP16(acc[mt][nt], a[mt], b[nt]);
        }
    };

    load_stage(0, 0);
    for (int c = 0; c < nch; c++) {
        if (c + 1 < nch) {
            load_stage(c + 1, (c + 1) & 1);
            asm volatile("cp.async.wait_group 1;" ::: "memory");
        } else {
            asm volatile("cp.async.wait_group 0;" ::: "memory");
        }
        __syncthreads();
        compute_stage(c & 1);
        __syncthreads();
    }

    // ---- epilogue ----
#pragma unroll
    for (int mt = 0; mt < 2; mt++)
#pragma unroll
    for (int h = 0; h < 2; h++) {
        int row = m0 + wm + mt * 16 + (lane >> 2) + h * 8;
        size_t rbase;
        if (EPI == 3) {
            int n  = row % 49;
            int wg = row / 49;
            int w  = wg & 63;
            int bb = wg >> 6;
            int hr = (w >> 3) * 7 + n / 7 + shift; if (hr >= 56) hr -= 56;
            int wc = (w & 7)  * 7 + n % 7 + shift; if (wc >= 56) wc -= 56;
            rbase = ((size_t)bb * 3136 + hr * 56 + wc) * 192;
        } else {
            rbase = (size_t)row * N;
        }
        int cb = n0 + wn + (lane & 3) * 2;
#pragma unroll
        for (int nt = 0; nt < 4; nt++) {
            int col = cb + nt * 8;
            float v0 = acc[mt][nt][h * 2 + 0] + bias[col];
            float v1 = acc[mt][nt][h * 2 + 1] + bias[col + 1];
            if (EPI == 0) {
                __half2 hp; hp.x = __float2half(v0); hp.y = __float2half(v1);
                *(__half2*)(Ch + rbase + col) = hp;
            } else if (EPI == 1) {
                float g0 = v0 * normcdff(v0);
                float g1 = v1 * normcdff(v1);
                __half2 hp; hp.x = __float2half(g0); hp.y = __float2half(g1);
                *(__half2*)(Ch + rbase + col) = hp;
            } else {
                if (EPI >= 2) {
                    float2 rr = *(const float2*)(res + rbase + col);
                    v0 += rr.x; v1 += rr.y;
                }
                float2 o; o.x = v0; o.y = v1;
                *(float2*)(Cf + rbase + col) = o;
            }
        }
    }
}

// ---------------- host launcher ----------------------------------------------
extern "C" void kernel_launch(void* const* d_in, const int* in_sizes, int n_in,
                              void* d_out, int out_size)
{
    const float* x    = (const float*)d_in[0];
    const float* n1g  = (const float*)d_in[1];
    const float* n1b  = (const float*)d_in[2];
    const float* qkvw = (const float*)d_in[3];
    const float* qkvb = (const float*)d_in[4];
    const float* bt   = (const float*)d_in[5];
    const float* pw   = (const float*)d_in[6];
    const float* pb   = (const float*)d_in[7];
    const float* n2g  = (const float*)d_in[8];
    const float* n2b  = (const float*)d_in[9];
    const float* f1w  = (const float*)d_in[10];
    const float* f1b  = (const float*)d_in[11];
    const float* f2w  = (const float*)d_in[12];
    const float* f2b  = (const float*)d_in[13];
    float* out = (float*)d_out;

    float *xbuf;
    __half *qkvh, *xn, *att, *hid, *wt;
    cudaGetSymbolAddress((void**)&qkvh, g_qkvh);
    cudaGetSymbolAddress((void**)&xbuf, g_xbuf);
    cudaGetSymbolAddress((void**)&xn,   g_xn);
    cudaGetSymbolAddress((void**)&att,  g_att);
    cudaGetSymbolAddress((void**)&hid,  g_hid);
    cudaGetSymbolAddress((void**)&wt,   g_wt);

    // weight transpose -> fp16 (both layers per launch)
    wprep_kernel<<<(2 * 110592 + 255) / 256, 256>>>(qkvw, wt,          192, 576, 442368);
    wprep_kernel<<<(2 * 36864  + 255) / 256, 256>>>(pw,   wt + 110592, 192, 192, 442368);
    wprep_kernel<<<(2 * 147456 + 255) / 256, 256>>>(f1w,  wt + 147456, 192, 768, 442368);
    wprep_kernel<<<(2 * 147456 + 255) / 256, 256>>>(f2w,  wt + 294912, 768, 192, 442368);

    for (int d = 0; d < 2; d++) {
        int shift = d ? 3 : 0;
        size_t L = (size_t)d * 442368;
        const float* xin = (d == 0) ? x : xbuf;   // running stream input
        // LN1 + shift + window partition -> fp16
        ln_kernel<<<TOK / 8, 256>>>(xin, n1g + d * 192, n1b + d * 192, xn, shift, 1);
        // QKV GEMM -> fp16 qkv
        tc_gemm<0><<<dim3(9, 784), 256>>>(xn, wt + L,
                                          qkvb + d * 576, nullptr, qkvh,
                                          nullptr, TOK, 576, 192, 0);
        // attention -> fp16
        attn_kernel<<<12288, 128>>>(qkvh, bt + d * 1014, att, shift ? 1 : 0);
        // proj GEMM + window reverse + unshift + residual -> xbuf
        tc_gemm<3><<<dim3(3, 784), 256>>>(att, wt + L + 110592,
                                          pb + d * 192, xbuf, nullptr,
                                          xin, TOK, 192, 192, shift);
        // LN2 -> fp16
        ln_kernel<<<TOK / 8, 256>>>(xbuf, n2g + d * 192, n2b + d * 192, xn, 0, 0);
        // FC1 + GELU -> fp16
        tc_gemm<1><<<dim3(12, 784), 256>>>(xn, wt + L + 147456,
                                           f1b + d * 768, nullptr, hid,
                                           nullptr, TOK, 768, 192, 0);
        // FC2 + residual; last layer writes d_out
        tc_gemm<2><<<dim3(3, 784), 256>>>(hid, wt + L + 294912,
                                          f2b + d * 192, (d == 1 ? out : xbuf), nullptr,
                                          xbuf, TOK, 192, 768, 0);
    }
}

// round 16
// speedup vs baseline: 1.4003x; 1.4003x over previous
#include <cuda_runtime.h>
#include <cuda_fp16.h>
#include <cstdint>
#include <math.h>

#define TOK 100352          // B * H * W tokens

// ---------------- scratch (device globals; no allocation allowed) -----------
__device__ __half  g_qkvh[(size_t)TOK * 576];   // qkv fp16, windowed rows
__device__ float   g_xbuf[(size_t)TOK * 192];   // running x (token layout)
__device__ __half  g_xn  [(size_t)TOK * 192];   // LN out fp16
__device__ __half  g_att [(size_t)TOK * 192];   // attention out fp16
__device__ __half  g_hid [(size_t)TOK * 768];   // fc1 out fp16
__device__ __half  g_wt  [2 * 442368];          // transposed weights fp16 [N,K]

// ---------------- helpers -----------------------------------------------------
__device__ __forceinline__ uint32_t smem_u32(const void* p) {
    uint32_t a;
    asm("{ .reg .u64 t; cvta.to.shared.u64 t, %1; cvt.u32.u64 %0, t; }" : "=r"(a) : "l"(p));
    return a;
}
#define CP_ASYNC16(dst, src) \
    asm volatile("cp.async.cg.shared.global [%0], [%1], 16;" :: "r"(dst), "l"(src))
#define CP_COMMIT()  asm volatile("cp.async.commit_group;" ::: "memory")
#define MMA_FP16(d, a, b) \
    asm volatile("mma.sync.aligned.m16n8k16.row.col.f32.f16.f16.f32 " \
        "{%0,%1,%2,%3}, {%4,%5,%6,%7}, {%8,%9}, {%0,%1,%2,%3};" \
        : "+f"((d)[0]), "+f"((d)[1]), "+f"((d)[2]), "+f"((d)[3]) \
        : "r"((a)[0]), "r"((a)[1]), "r"((a)[2]), "r"((a)[3]), "r"((b)[0]), "r"((b)[1]))

// ---------------- weight transpose (both layers), fp16 ----------------------
__global__ void wprep_kernel(const float* __restrict__ W, __half* __restrict__ T,
                             int K, int N, int strideT) {
    int i = blockIdx.x * blockDim.x + threadIdx.x;
    int perL = K * N;
    if (i >= 2 * perL) return;
    int d = i / perL, r = i - d * perL;
    int n = r / K, k = r - n * K;
    T[(size_t)d * strideT + n * K + k] = __float2half(W[(size_t)d * perL + (size_t)k * N + n]);
}

// ---------------- LayerNorm (+ optional shift/window gather), fp16 out -------
__global__ void ln_kernel(const float* __restrict__ x, const float* __restrict__ g,
                          const float* __restrict__ bta, __half* __restrict__ oh,
                          int shift, int gather)
{
    int warp = (blockIdx.x * blockDim.x + threadIdx.x) >> 5;
    int lane = threadIdx.x & 31;
    if (warp >= TOK) return;
    int row = warp;
    const float* xi;
    if (gather) {
        int n  = row % 49;
        int wg = row / 49;
        int w  = wg & 63;
        int b  = wg >> 6;
        int hr = (w >> 3) * 7 + n / 7 + shift; if (hr >= 56) hr -= 56;
        int wc = (w & 7)  * 7 + n % 7 + shift; if (wc >= 56) wc -= 56;
        xi = x + ((size_t)b * 3136 + hr * 56 + wc) * 192;
    } else {
        xi = x + (size_t)row * 192;
    }
    float v[6];
    float s = 0.f, sq = 0.f;
#pragma unroll
    for (int q = 0; q < 6; q++) {
        v[q] = xi[lane + 32 * q];
        s += v[q]; sq += v[q] * v[q];
    }
#pragma unroll
    for (int o = 16; o; o >>= 1) {
        s  += __shfl_xor_sync(0xffffffffu, s,  o);
        sq += __shfl_xor_sync(0xffffffffu, sq, o);
    }
    float mean = s * (1.f / 192.f);
    float var  = sq * (1.f / 192.f) - mean * mean;
    float rstd = rsqrtf(var + 1e-5f);
#pragma unroll
    for (int q = 0; q < 6; q++) {
        int ch = lane + 32 * q;
        float y = (v[q] - mean) * rstd * g[ch] + bta[ch];
        oh[(size_t)row * 192 + ch] = __float2half(y);
    }
}

// ---------------- Windowed attention -----------------------------------------
// One block per (window, head). qkv fp16; coalesced per-element loads.
// Q rows in registers, K rows at stride-36 floats, V transposed (stride 52).
// Relative-position bias staged in smem (169 floats per head).
__global__ void attn_kernel(const __half* __restrict__ qkv, const float* __restrict__ bt,
                            __half* __restrict__ oh, int shifted)
{
    int blk  = blockIdx.x;
    int head = blk % 6;
    int win  = blk / 6;          // 0..2047
    int w    = win & 63;
    int wh   = w >> 3, ww = w & 7;

    __shared__ float4 qs4[49 * 8];
    __shared__ float4 ks4[49 * 9];       // row stride 36 floats
    __shared__ float4 vs4[32 * 13];      // V transposed: [d][j], row stride 52 floats
    __shared__ float  prow[4][52];
    __shared__ float  sb_bias[169];      // 13x13 relative-position bias, this head
    __shared__ int    lab[49];

    int tid = threadIdx.x;
    const float scale = 0.17677669529663687f;  // 1/sqrt(32)
    const __half* base = qkv + (size_t)win * 49 * 576 + head * 32;
    float* qsf = (float*)qs4;
    float* ksf = (float*)ks4;
    float* vsf = (float*)vs4;
    for (int i = tid; i < 49 * 32; i += 128) {
        int t = i >> 5, d = i & 31;
        const __half* p = base + (size_t)t * 576 + d;
        qsf[t * 32 + d] = __half2float(p[0]) * scale;
        ksf[t * 36 + d] = __half2float(p[192]);
        vsf[d * 52 + t] = __half2float(p[384]);      // transposed
    }
    for (int i = tid; i < 169; i += 128)
        sb_bias[i] = bt[i * 6 + head];
    if (shifted && tid < 49) {
        int r = tid / 7, c = tid % 7;
        int hr = wh * 7 + r, wc = ww * 7 + c;
        int lr = (hr < 49) ? 0 : (hr < 53 ? 1 : 2);
        int lc = (wc < 49) ? 0 : (wc < 53 ? 1 : 2);
        lab[tid] = lr * 3 + lc;
    }
    __syncthreads();

    int warp = tid >> 5, lane = tid & 31;
    for (int i = warp; i < 49; i += 4) {
        float4 q[8];
#pragma unroll
        for (int t = 0; t < 8; t++) q[t] = qs4[i * 8 + t];
        int yi = i / 7, xi = i % 7;
        float s0, s1 = -1e30f;
        {
            int j = lane;
            float acc = 0.f;
#pragma unroll
            for (int t = 0; t < 8; t++) {
                float4 k = ks4[j * 9 + t];
                acc += q[t].x * k.x + q[t].y * k.y + q[t].z * k.z + q[t].w * k.w;
            }
            int yj = j / 7, xj = j % 7;
            acc += sb_bias[(yi - yj + 6) * 13 + (xi - xj + 6)];
            if (shifted && lab[i] != lab[j]) acc -= 100.f;
            s0 = acc;
        }
        if (lane + 32 < 49) {
            int j = lane + 32;
            float acc = 0.f;
#pragma unroll
            for (int t = 0; t < 8; t++) {
                float4 k = ks4[j * 9 + t];
                acc += q[t].x * k.x + q[t].y * k.y + q[t].z * k.z + q[t].w * k.w;
            }
            int yj = j / 7, xj = j % 7;
            acc += sb_bias[(yi - yj + 6) * 13 + (xi - xj + 6)];
            if (shifted && lab[i] != lab[j]) acc -= 100.f;
            s1 = acc;
        }
        float m = fmaxf(s0, s1);
#pragma unroll
        for (int o = 16; o; o >>= 1) m = fmaxf(m, __shfl_xor_sync(0xffffffffu, m, o));
        float e0 = __expf(s0 - m);
        float e1 = (lane + 32 < 49) ? __expf(s1 - m) : 0.f;
        float sum = e0 + e1;
#pragma unroll
        for (int o = 16; o; o >>= 1) sum += __shfl_xor_sync(0xffffffffu, sum, o);
        float inv = 1.f / sum;
        prow[warp][lane] = e0 * inv;
        if (lane + 32 < 49) prow[warp][lane + 32] = e1 * inv;
        __syncwarp();
        // PV: lane = output dim d; vectorized over j (12 x float4 + 1 tail)
        const float4* pr4 = (const float4*)&prow[warp][0];
        float acc = 0.f;
#pragma unroll
        for (int q4 = 0; q4 < 12; q4++) {
            float4 p = pr4[q4];
            float4 v = vs4[lane * 13 + q4];
            acc += p.x * v.x + p.y * v.y + p.z * v.z + p.w * v.w;
        }
        acc += prow[warp][48] * vsf[lane * 52 + 48];
        oh[((size_t)win * 49 + i) * 192 + head * 32 + lane] = __float2half(acc);
        __syncwarp();
    }
}

// ---------------- warp-MMA fp16 GEMM (single-term, K-chunk 32) ---------------
// CTA 128x64, 256 threads (4x2 warps, warp tile 32x32), K chunks of 32,
// 2-stage cp.async pipeline, XOR-swizzled smem. 1 mma term: A*B.
// EPI 0: +bias -> fp16 Ch       EPI 1: +bias, GELU -> fp16 Ch
// EPI 2: +bias +res -> fp32 Cf  EPI 3: +bias, window-reverse remap, +res -> fp32
#define STG 6144   // halfs per stage (12288 B): A 8K + B 4K

template <int EPI>
__global__ void __launch_bounds__(256)
tc_gemm(const __half* __restrict__ Ah, const __half* __restrict__ Bw,
        const float* __restrict__ bias, float* __restrict__ Cf,
        __half* __restrict__ Ch,
        const float* __restrict__ res, int M, int N, int K, int shift)
{
    __shared__ __half smem[2 * STG];   // 24576 B
    const int tid  = threadIdx.x;
    const int wid  = tid >> 5, lane = tid & 31;
    const int m0   = blockIdx.y * 128, n0 = blockIdx.x * 64;
    const int wm   = (wid & 3) * 32;          // warp row offset
    const int wn   = (wid >> 2) * 32;         // warp col offset
    const uint32_t sbase = smem_u32(smem);

    float acc[2][4][4];
#pragma unroll
    for (int a = 0; a < 2; a++)
#pragma unroll
        for (int b = 0; b < 4; b++)
#pragma unroll
            for (int c = 0; c < 4; c++) acc[a][b][c] = 0.f;

    const int nch = K >> 5;

    // ---- stage loader: A 128x32 + B 64x32, 16B cp.async each ----
    auto load_stage = [&](int c, int s) {
        int kc = c * 32;
        uint32_t st = sbase + s * (STG * 2);
#pragma unroll
        for (int t = 0; t < 2; t++) {
            int local = tid + t * 256;                // 0..511
            int row = local >> 2, seg = local & 3;
            const __half* src = Ah + (size_t)(m0 + row) * K + kc + seg * 8;
            uint32_t d = st + row * 64 + ((seg ^ (row & 3)) * 16);
            CP_ASYNC16(d, src);
        }
        {
            int row = tid >> 2, seg = tid & 3;
            const __half* src = Bw + (size_t)(n0 + row) * K + kc + seg * 8;
            uint32_t d = st + 8192 + row * 64 + ((seg ^ (row & 3)) * 16);
            CP_ASYNC16(d, src);
        }
        CP_COMMIT();
    };

    const int i8  = lane & 7;     // ldmatrix row-within-tile
    const int mat = lane >> 3;    // ldmatrix matrix index

    auto compute_stage = [&](int s) {
        uint32_t st = sbase + s * (STG * 2);
        uint32_t aB = st;
        uint32_t bB = st + 8192;
#pragma unroll
        for (int ks = 0; ks < 2; ks++) {
            uint32_t a[2][4], b[4][2];
#pragma unroll
            for (int mt = 0; mt < 2; mt++) {
                int row = wm + mt * 16 + ((mat & 1) << 3) + i8;
                int cch = ks * 2 + (mat >> 1);            // 8-elem chunk idx
                uint32_t addr = aB + row * 64 + ((cch ^ (row & 3)) << 4);
                asm volatile("ldmatrix.sync.aligned.m8n8.x4.shared.b16 {%0,%1,%2,%3}, [%4];"
                    : "=r"(a[mt][0]), "=r"(a[mt][1]), "=r"(a[mt][2]), "=r"(a[mt][3])
                    : "r"(addr));
            }
#pragma unroll
            for (int p = 0; p < 2; p++) {
                // B fragment: [N,K] K-contiguous -> NON-trans ldmatrix
                int row = wn + p * 16 + ((mat >> 1) << 3) + i8;
                int cch = ks * 2 + (mat & 1);
                uint32_t addr = bB + row * 64 + ((cch ^ (row & 3)) << 4);
                uint32_t r0, r1, r2, r3;
                asm volatile("ldmatrix.sync.aligned.m8n8.x4.shared.b16 {%0,%1,%2,%3}, [%4];"
                    : "=r"(r0), "=r"(r1), "=r"(r2), "=r"(r3) : "r"(addr));
                b[p * 2][0] = r0; b[p * 2][1] = r1;
                b[p * 2 + 1][0] = r2; b[p * 2 + 1][1] = r3;
            }
#pragma unroll
            for (int mt = 0; mt < 2; mt++)
#pragma unroll
                for (int nt = 0; nt < 4; nt++)
                    MMA_FP16(acc[mt][nt], a[mt], b[nt]);
        }
    };

    load_stage(0, 0);
    for (int c = 0; c < nch; c++) {
        if (c + 1 < nch) {
            load_stage(c + 1, (c + 1) & 1);
            asm volatile("cp.async.wait_group 1;" ::: "memory");
        } else {
            asm volatile("cp.async.wait_group 0;" ::: "memory");
        }
        __syncthreads();
        compute_stage(c & 1);
        __syncthreads();
    }

    // ---- epilogue ----
#pragma unroll
    for (int mt = 0; mt < 2; mt++)
#pragma unroll
    for (int h = 0; h < 2; h++) {
        int row = m0 + wm + mt * 16 + (lane >> 2) + h * 8;
        size_t rbase;
        if (EPI == 3) {
            int n  = row % 49;
            int wg = row / 49;
            int w  = wg & 63;
            int bb = wg >> 6;
            int hr = (w >> 3) * 7 + n / 7 + shift; if (hr >= 56) hr -= 56;
            int wc = (w & 7)  * 7 + n % 7 + shift; if (wc >= 56) wc -= 56;
            rbase = ((size_t)bb * 3136 + hr * 56 + wc) * 192;
        } else {
            rbase = (size_t)row * N;
        }
        int cb = n0 + wn + (lane & 3) * 2;
#pragma unroll
        for (int nt = 0; nt < 4; nt++) {
            int col = cb + nt * 8;
            float v0 = acc[mt][nt][h * 2 + 0] + bias[col];
            float v1 = acc[mt][nt][h * 2 + 1] + bias[col + 1];
            if (EPI == 0) {
                __half2 hp; hp.x = __float2half(v0); hp.y = __float2half(v1);
                *(__half2*)(Ch + rbase + col) = hp;
            } else if (EPI == 1) {
                float g0 = v0 * normcdff(v0);
                float g1 = v1 * normcdff(v1);
                __half2 hp; hp.x = __float2half(g0); hp.y = __float2half(g1);
                *(__half2*)(Ch + rbase + col) = hp;
            } else {
                if (EPI >= 2) {
                    float2 rr = *(const float2*)(res + rbase + col);
                    v0 += rr.x; v1 += rr.y;
                }
                float2 o; o.x = v0; o.y = v1;
                *(float2*)(Cf + rbase + col) = o;
            }
        }
    }
}

// ---------------- host launcher ----------------------------------------------
extern "C" void kernel_launch(void* const* d_in, const int* in_sizes, int n_in,
                              void* d_out, int out_size)
{
    const float* x    = (const float*)d_in[0];
    const float* n1g  = (const float*)d_in[1];
    const float* n1b  = (const float*)d_in[2];
    const float* qkvw = (const float*)d_in[3];
    const float* qkvb = (const float*)d_in[4];
    const float* bt   = (const float*)d_in[5];
    const float* pw   = (const float*)d_in[6];
    const float* pb   = (const float*)d_in[7];
    const float* n2g  = (const float*)d_in[8];
    const float* n2b  = (const float*)d_in[9];
    const float* f1w  = (const float*)d_in[10];
    const float* f1b  = (const float*)d_in[11];
    const float* f2w  = (const float*)d_in[12];
    const float* f2b  = (const float*)d_in[13];
    float* out = (float*)d_out;

    float *xbuf;
    __half *qkvh, *xn, *att, *hid, *wt;
    cudaGetSymbolAddress((void**)&qkvh, g_qkvh);
    cudaGetSymbolAddress((void**)&xbuf, g_xbuf);
    cudaGetSymbolAddress((void**)&xn,   g_xn);
    cudaGetSymbolAddress((void**)&att,  g_att);
    cudaGetSymbolAddress((void**)&hid,  g_hid);
    cudaGetSymbolAddress((void**)&wt,   g_wt);

    // weight transpose -> fp16 (both layers per launch)
    wprep_kernel<<<(2 * 110592 + 255) / 256, 256>>>(qkvw, wt,          192, 576, 442368);
    wprep_kernel<<<(2 * 36864  + 255) / 256, 256>>>(pw,   wt + 110592, 192, 192, 442368);
    wprep_kernel<<<(2 * 147456 + 255) / 256, 256>>>(f1w,  wt + 147456, 192, 768, 442368);
    wprep_kernel<<<(2 * 147456 + 255) / 256, 256>>>(f2w,  wt + 294912, 768, 192, 442368);

    for (int d = 0; d < 2; d++) {
        int shift = d ? 3 : 0;
        size_t L = (size_t)d * 442368;
        const float* xin = (d == 0) ? x : xbuf;   // running stream input
        // LN1 + shift + window partition -> fp16
        ln_kernel<<<TOK / 8, 256>>>(xin, n1g + d * 192, n1b + d * 192, xn, shift, 1);
        // QKV GEMM -> fp16 qkv
        tc_gemm<0><<<dim3(9, 784), 256>>>(xn, wt + L,
                                          qkvb + d * 576, nullptr, qkvh,
                                          nullptr, TOK, 576, 192, 0);
        // attention -> fp16
        attn_kernel<<<12288, 128>>>(qkvh, bt + d * 1014, att, shift ? 1 : 0);
        // proj GEMM + window reverse + unshift + residual -> xbuf
        tc_gemm<3><<<dim3(3, 784), 256>>>(att, wt + L + 110592,
                                          pb + d * 192, xbuf, nullptr,
                                          xin, TOK, 192, 192, shift);
        // LN2 -> fp16
        ln_kernel<<<TOK / 8, 256>>>(xbuf, n2g + d * 192, n2b + d * 192, xn, 0, 0);
        // FC1 + GELU -> fp16
        tc_gemm<1><<<dim3(12, 784), 256>>>(xn, wt + L + 147456,
                                           f1b + d * 768, nullptr, hid,
                                           nullptr, TOK, 768, 192, 0);
        // FC2 + residual; last layer writes d_out
        tc_gemm<2><<<dim3(3, 784), 256>>>(hid, wt + L + 294912,
                                          f2b + d * 192, (d == 1 ? out : xbuf), nullptr,
                                          xbuf, TOK, 192, 768, 0);
    }
}